// round 3
// baseline (speedup 1.0000x reference)
#include <cuda_runtime.h>

// SSIM loss, fused single pass, f32x2-packed + row-pair pipelined.
// pred/target: (16,3,512,512) fp32. out: 16 fp32 (1 - mean ssim per sample).
//
// Rows stored in smem as interleaved (p,t) float2 -> packed f32x2 math:
//   sumPT = (hp,ht), sumSQ = (hpp,htt) in one chain each; hpt scalar.
// Vertical 11-row sliding sums via per-thread ring (smem, conflict-free).
// 2 rows per iteration: one barrier / 2 rows, 6 independent FMA chains.
// Grid: 48 images x 3 strips = 144 blocks, 128 threads x 4 cols.

#define WIDTH   512
#define HEIGHT  512
#define PADR    5
#define NT      128
#define NSTRIP  3
#define STRIPH  171
#define RS2     528
#define NBLOCKS (48 * NSTRIP)

// smem byte offsets
#define OF_SQ   45056
#define OF_X    90112
#define OF_ROW  112640
#define OF_RED  129536
#define SMEM_SZ 130048

typedef unsigned long long u64;

__device__ float g_partials[NBLOCKS];

__device__ __forceinline__ u64 pk2(float a, float b) {
    u64 r; asm("mov.b64 %0,{%1,%2};" : "=l"(r) : "f"(a), "f"(b)); return r;
}
__device__ __forceinline__ float2 up2(u64 a) {
    float2 r; asm("mov.b64 {%0,%1},%2;" : "=f"(r.x), "=f"(r.y) : "l"(a)); return r;
}
__device__ __forceinline__ u64 add2(u64 a, u64 b) {
    u64 r; asm("add.rn.f32x2 %0,%1,%2;" : "=l"(r) : "l"(a), "l"(b)); return r;
}
__device__ __forceinline__ u64 mul2(u64 a, u64 b) {
    u64 r; asm("mul.rn.f32x2 %0,%1,%2;" : "=l"(r) : "l"(a), "l"(b)); return r;
}
__device__ __forceinline__ u64 fma2(u64 a, u64 b, u64 c) {
    u64 r; asm("fma.rn.f32x2 %0,%1,%2,%3;" : "=l"(r) : "l"(a), "l"(b), "l"(c)); return r;
}

// Horizontal 11-tap windows for 4 output columns.
// row: interleaved (p,t) float2 buffer (image x at idx x+8; pads zeroed).
// own[0..3]: this thread's 4 packed pixels (idx x0+8..x0+11) kept in regs.
__device__ __forceinline__ void hwin(const float2* __restrict__ row, int x0,
                                     const u64 own[4], u64 M1,
                                     u64 hPT[4], u64 hSQ[4], float hX[4])
{
    u64 pt[14];
    float2 e0 = row[x0 + 3];
    pt[0] = pk2(e0.x, e0.y);
    {
        ulonglong2 q1 = *(const ulonglong2*)(row + x0 + 4);
        ulonglong2 q2 = *(const ulonglong2*)(row + x0 + 6);
        pt[1] = q1.x; pt[2] = q1.y; pt[3] = q2.x; pt[4] = q2.y;
    }
    pt[5] = own[0]; pt[6] = own[1]; pt[7] = own[2]; pt[8] = own[3];
    {
        ulonglong2 q3 = *(const ulonglong2*)(row + x0 + 12);
        ulonglong2 q4 = *(const ulonglong2*)(row + x0 + 14);
        pt[9] = q3.x; pt[10] = q3.y; pt[11] = q4.x; pt[12] = q4.y;
    }
    float2 e13 = row[x0 + 16];
    pt[13] = pk2(e13.x, e13.y);

    u64 s = pt[0];
    u64 q = mul2(pt[0], pt[0]);
    float2 f0 = up2(pt[0]);
    float x = f0.x * f0.y;
#pragma unroll
    for (int k = 1; k < 11; k++) {
        s = add2(s, pt[k]);
        q = fma2(pt[k], pt[k], q);
        float2 g = up2(pt[k]);
        x = fmaf(g.x, g.y, x);
    }
    hPT[0] = s; hSQ[0] = q; hX[0] = x;
#pragma unroll
    for (int j = 1; j < 4; j++) {
        u64 nw = pt[j + 10], od = pt[j - 1];
        s = add2(s, nw);
        s = fma2(od, M1, s);             // s -= od
        q = fma2(nw, nw, q);
        q = fma2(od, mul2(od, M1), q);   // q -= od^2
        float2 fn = up2(nw), fo = up2(od);
        x = fmaf(fn.x, fn.y, x);
        x = fmaf(-fo.x, fo.y, x);
        hPT[j] = s; hSQ[j] = q; hX[j] = x;
    }
}

// Vertical sliding-sum update for one row + optional SSIM emit.
__device__ __forceinline__ void vrow(char* smbase, int slot, int tid,
    const u64 hPT[4], const u64 hSQ[4], const float hX[4],
    u64 SPT[4], u64 SSQ[4], float SX[4],
    u64 M1, u64 INV2, float inv, bool emit, float& acc)
{
    ulonglong2* rpt = (ulonglong2*)(smbase)         + (slot * 2) * NT + tid;
    ulonglong2* rsq = (ulonglong2*)(smbase + OF_SQ) + (slot * 2) * NT + tid;
    float4*     rx  = (float4*)(smbase + OF_X)      + slot * NT + tid;
    ulonglong2 o0 = rpt[0], o1 = rpt[NT];
    ulonglong2 p0 = rsq[0], p1 = rsq[NT];
    float4 ox = *rx;
    SPT[0] = add2(SPT[0], fma2(o0.x, M1, hPT[0]));
    SPT[1] = add2(SPT[1], fma2(o0.y, M1, hPT[1]));
    SPT[2] = add2(SPT[2], fma2(o1.x, M1, hPT[2]));
    SPT[3] = add2(SPT[3], fma2(o1.y, M1, hPT[3]));
    SSQ[0] = add2(SSQ[0], fma2(p0.x, M1, hSQ[0]));
    SSQ[1] = add2(SSQ[1], fma2(p0.y, M1, hSQ[1]));
    SSQ[2] = add2(SSQ[2], fma2(p1.x, M1, hSQ[2]));
    SSQ[3] = add2(SSQ[3], fma2(p1.y, M1, hSQ[3]));
    SX[0] += hX[0] - ox.x;
    SX[1] += hX[1] - ox.y;
    SX[2] += hX[2] - ox.z;
    SX[3] += hX[3] - ox.w;
    rpt[0]  = make_ulonglong2(hPT[0], hPT[1]);
    rpt[NT] = make_ulonglong2(hPT[2], hPT[3]);
    rsq[0]  = make_ulonglong2(hSQ[0], hSQ[1]);
    rsq[NT] = make_ulonglong2(hSQ[2], hSQ[3]);
    *rx = make_float4(hX[0], hX[1], hX[2], hX[3]);
    if (emit) {
#pragma unroll
        for (int c = 0; c < 4; c++) {
            u64 m   = mul2(SPT[c], INV2);    // (mu_x, mu_y)
            u64 e   = mul2(SSQ[c], INV2);    // (E[x^2], E[y^2])
            u64 msq = mul2(m, m);            // (mu_x^2, mu_y^2)
            float2 mf = up2(m), ef = up2(e), ms = up2(msq);
            float exy = SX[c] * inv;
            float m12 = mf.x * mf.y;
            float num = fmaf(2.f, m12, 1e-4f) * fmaf(2.f, exy - m12, 9e-4f);
            float den = (ms.x + ms.y + 1e-4f)
                      * ((ef.x - ms.x) + (ef.y - ms.y) + 9e-4f);
            acc += __saturatef(__fdividef(num, den));
        }
    }
}

__global__ __launch_bounds__(NT, 1)
void ssim_main_kernel(const float* __restrict__ pred, const float* __restrict__ targ)
{
    extern __shared__ char sm[];
    float2* rowbuf = (float2*)(sm + OF_ROW);   // [4][RS2] interleaved (p,t)
    float*  red    = (float*)(sm + OF_RED);

    const int tid   = threadIdx.x;
    const int bid   = blockIdx.x;
    const int img   = bid / NSTRIP;
    const int strip = bid - img * NSTRIP;
    const int r0    = strip * STRIPH;
    const int r1    = min(HEIGHT, r0 + STRIPH);
    const int yend  = r1 + PADR;
    const int emit0 = r0 + PADR;

    const float* __restrict__ P = pred + (size_t)img * (WIDTH * HEIGHT);
    const float* __restrict__ T = targ + (size_t)img * (WIDTH * HEIGHT);
    const int x0 = tid * 4;

    const u64 M1   = pk2(-1.f, -1.f);
    const float inv = 1.f / 121.f;
    const u64 INV2 = pk2(inv, inv);

    // zero ring (per-thread private slots; no sync needed)
    {
        ulonglong2 z2 = make_ulonglong2(0ull, 0ull);
        float4 z4 = make_float4(0.f, 0.f, 0.f, 0.f);
#pragma unroll
        for (int s = 0; s < 11; s++) {
            ((ulonglong2*)sm)[(s * 2 + 0) * NT + tid] = z2;
            ((ulonglong2*)sm)[(s * 2 + 1) * NT + tid] = z2;
            ((ulonglong2*)(sm + OF_SQ))[(s * 2 + 0) * NT + tid] = z2;
            ((ulonglong2*)(sm + OF_SQ))[(s * 2 + 1) * NT + tid] = z2;
            ((float4*)(sm + OF_X))[s * NT + tid] = z4;
        }
    }
    // zero pads of 4 row buffers: idx 3..7 (x=-5..-1) and 520..524 (x=512..516)
    if (tid < 40) {
        int r = tid / 10, k = tid % 10;
        int idx = (k < 5) ? (3 + k) : (520 + (k - 5));
        rowbuf[r * RS2 + idx] = make_float2(0.f, 0.f);
    }

    u64 SPT[4] = {0, 0, 0, 0}, SSQ[4] = {0, 0, 0, 0};
    float SX[4] = {0.f, 0.f, 0.f, 0.f};
    float acc = 0.f;
    int slot = 0;

    const int start = r0 - PADR;
    float4 cp0 = {}, ct0 = {}, cp1 = {}, ct1 = {};
    if (start >= 0 && start < HEIGHT) {
        cp0 = *(const float4*)(P + (size_t)start * WIDTH + x0);
        ct0 = *(const float4*)(T + (size_t)start * WIDTH + x0);
    }
    if (start + 1 >= 0 && start + 1 < HEIGHT) {
        cp1 = *(const float4*)(P + (size_t)(start + 1) * WIDTH + x0);
        ct1 = *(const float4*)(T + (size_t)(start + 1) * WIDTH + x0);
    }

    __syncthreads();   // pads visible

    for (int base = start; base < yend; base += 2) {
        const int pb = (base >> 1) & 1;
        float2* rA = rowbuf + (pb * 2 + 0) * RS2;
        float2* rB = rowbuf + (pb * 2 + 1) * RS2;
        const bool vA = (base >= 0) && (base < HEIGHT);
        const bool vB = (base + 1 >= 0) && (base + 1 < HEIGHT);

        u64 ownA[4], ownB[4];
        if (vA) {
            ownA[0] = pk2(cp0.x, ct0.x); ownA[1] = pk2(cp0.y, ct0.y);
            ownA[2] = pk2(cp0.z, ct0.z); ownA[3] = pk2(cp0.w, ct0.w);
            float4* d = (float4*)(rA + x0 + 8);
            d[0] = make_float4(cp0.x, ct0.x, cp0.y, ct0.y);
            d[1] = make_float4(cp0.z, ct0.z, cp0.w, ct0.w);
        }
        if (vB) {
            ownB[0] = pk2(cp1.x, ct1.x); ownB[1] = pk2(cp1.y, ct1.y);
            ownB[2] = pk2(cp1.z, ct1.z); ownB[3] = pk2(cp1.w, ct1.w);
            float4* d = (float4*)(rB + x0 + 8);
            d[0] = make_float4(cp1.x, ct1.x, cp1.y, ct1.y);
            d[1] = make_float4(cp1.z, ct1.z, cp1.w, ct1.w);
        }
        // prefetch next row pair (hidden behind this pair's compute)
        {
            int yn0 = base + 2, yn1 = base + 3;
            if (yn0 >= 0 && yn0 < HEIGHT) {
                cp0 = *(const float4*)(P + (size_t)yn0 * WIDTH + x0);
                ct0 = *(const float4*)(T + (size_t)yn0 * WIDTH + x0);
            }
            if (yn1 >= 0 && yn1 < HEIGHT) {
                cp1 = *(const float4*)(P + (size_t)yn1 * WIDTH + x0);
                ct1 = *(const float4*)(T + (size_t)yn1 * WIDTH + x0);
            }
        }
        __syncthreads();   // row pair visible (alternating pair-buffers)

        u64 hPT[4], hSQ[4]; float hX[4];
        if (vA) {
            hwin(rA, x0, ownA, M1, hPT, hSQ, hX);
        } else {
#pragma unroll
            for (int c = 0; c < 4; c++) { hPT[c] = 0; hSQ[c] = 0; hX[c] = 0.f; }
        }
        vrow(sm, slot, tid, hPT, hSQ, hX, SPT, SSQ, SX, M1, INV2, inv,
             base >= emit0, acc);

        int slotB = slot + 1; if (slotB == 11) slotB = 0;
        if (vB) {
            hwin(rB, x0, ownB, M1, hPT, hSQ, hX);
        } else {
#pragma unroll
            for (int c = 0; c < 4; c++) { hPT[c] = 0; hSQ[c] = 0; hX[c] = 0.f; }
        }
        vrow(sm, slotB, tid, hPT, hSQ, hX, SPT, SSQ, SX, M1, INV2, inv,
             (base + 1 >= emit0) && (base + 1 < yend), acc);

        slot += 2; if (slot >= 11) slot -= 11;
    }

    // deterministic block reduction
    red[tid] = acc;
    __syncthreads();
#pragma unroll
    for (int s = NT / 2; s > 0; s >>= 1) {
        if (tid < s) red[tid] += red[tid + s];
        __syncthreads();
    }
    if (tid == 0) g_partials[bid] = red[0];
}

__global__ void ssim_finalize_kernel(float* __restrict__ out) {
    const int i = threadIdx.x;
    if (i < 16) {
        float s = 0.f;
#pragma unroll
        for (int j = 0; j < 3 * NSTRIP; j++) s += g_partials[i * (3 * NSTRIP) + j];
        out[i] = 1.f - s * (1.f / (3.f * 512.f * 512.f));
    }
}

extern "C" void kernel_launch(void* const* d_in, const int* in_sizes, int n_in,
                              void* d_out, int out_size) {
    const float* pred = (const float*)d_in[0];
    const float* targ = (const float*)d_in[1];
    cudaFuncSetAttribute(ssim_main_kernel,
                         cudaFuncAttributeMaxDynamicSharedMemorySize, SMEM_SZ);
    ssim_main_kernel<<<NBLOCKS, NT, SMEM_SZ>>>(pred, targ);
    ssim_finalize_kernel<<<1, 32>>>((float*)d_out);
}

// round 5
// speedup vs baseline: 1.6080x; 1.6080x over previous
#include <cuda_runtime.h>

// SSIM loss, fused single pass, f32x2-packed, NT=256 (2 warps/SMSP), 2 cols/thread.
// pred/target: (16,3,512,512) fp32. out: 16 fp32 (1 - mean ssim per sample).
//
// Rows in smem as interleaved (p,t) float2 -> packed f32x2 math.
// Vertical 11-row sliding sums via per-thread ring (smem, conflict-free).
// 2 rows per iteration: one barrier / 2 rows.
// Grid: 48 images x 3 strips = 144 blocks, 256 threads x 2 cols.

#define WIDTH   512
#define HEIGHT  512
#define PADR    5
#define NT      256
#define NSTRIP  3
#define STRIPH  171
#define RS2     528
#define NBLOCKS (48 * NSTRIP)

// smem byte offsets
#define OF_PT   0
#define OF_SQ   45056          // 11*256*16
#define OF_X    90112          // + 11*256*16
#define OF_ROW  112640         // + 11*256*8
#define OF_RED  129536         // + 4*528*8
#define SMEM_SZ 130560

typedef unsigned long long u64;

__device__ float g_partials[NBLOCKS];

__device__ __forceinline__ u64 pk2(float a, float b) {
    u64 r; asm("mov.b64 %0,{%1,%2};" : "=l"(r) : "f"(a), "f"(b)); return r;
}
__device__ __forceinline__ float2 up2(u64 a) {
    float2 r; asm("mov.b64 {%0,%1},%2;" : "=f"(r.x), "=f"(r.y) : "l"(a)); return r;
}
__device__ __forceinline__ u64 add2(u64 a, u64 b) {
    u64 r; asm("add.rn.f32x2 %0,%1,%2;" : "=l"(r) : "l"(a), "l"(b)); return r;
}
__device__ __forceinline__ u64 mul2(u64 a, u64 b) {
    u64 r; asm("mul.rn.f32x2 %0,%1,%2;" : "=l"(r) : "l"(a), "l"(b)); return r;
}
__device__ __forceinline__ u64 fma2(u64 a, u64 b, u64 c) {
    u64 r; asm("fma.rn.f32x2 %0,%1,%2,%3;" : "=l"(r) : "l"(a), "l"(b), "l"(c)); return r;
}

// Horizontal 11-tap windows for 2 output columns (x0, x0+1).
// Window covers idx [x0+3, x0+14]; own0/own1 = idx x0+8, x0+9 kept in regs.
__device__ __forceinline__ void hwin2(const float2* __restrict__ row, int x0,
                                      u64 own0, u64 own1, u64 M1,
                                      u64 hPT[2], u64 hSQ[2], float hX[2])
{
    u64 pt[12];
    {
        ulonglong2 a = *(const ulonglong2*)(row + x0 + 2);   // x0+2, x0+3
        ulonglong2 b = *(const ulonglong2*)(row + x0 + 4);
        ulonglong2 c = *(const ulonglong2*)(row + x0 + 6);
        pt[0] = a.y; pt[1] = b.x; pt[2] = b.y; pt[3] = c.x; pt[4] = c.y;
    }
    pt[5] = own0; pt[6] = own1;
    {
        ulonglong2 d = *(const ulonglong2*)(row + x0 + 10);
        ulonglong2 e = *(const ulonglong2*)(row + x0 + 12);
        ulonglong2 f = *(const ulonglong2*)(row + x0 + 14);
        pt[7] = d.x; pt[8] = d.y; pt[9] = e.x; pt[10] = e.y; pt[11] = f.x;
    }

    u64 s = pt[0];
    u64 q = mul2(pt[0], pt[0]);
    float2 f0 = up2(pt[0]);
    float x = f0.x * f0.y;
#pragma unroll
    for (int k = 1; k < 11; k++) {
        s = add2(s, pt[k]);
        q = fma2(pt[k], pt[k], q);
        float2 g = up2(pt[k]);
        x = fmaf(g.x, g.y, x);
    }
    hPT[0] = s; hSQ[0] = q; hX[0] = x;
    // slide by one
    s = add2(s, pt[11]);
    s = fma2(pt[0], M1, s);
    q = fma2(pt[11], pt[11], q);
    q = fma2(pt[0], mul2(pt[0], M1), q);
    float2 fn = up2(pt[11]);
    x = fmaf(fn.x, fn.y, x);
    x = fmaf(-f0.x, f0.y, x);
    hPT[1] = s; hSQ[1] = q; hX[1] = x;
}

// Vertical sliding-sum update for one row + optional SSIM emit (2 cols).
__device__ __forceinline__ void vrow2(char* smbase, int slot, int tid,
    const u64 hPT[2], const u64 hSQ[2], const float hX[2],
    u64 SPT[2], u64 SSQ[2], float SX[2],
    u64 M1, u64 INV2, float inv, bool emit, float& acc)
{
    ulonglong2* rpt = (ulonglong2*)(smbase + OF_PT) + slot * NT + tid;
    ulonglong2* rsq = (ulonglong2*)(smbase + OF_SQ) + slot * NT + tid;
    float2*     rx  = (float2*)(smbase + OF_X)      + slot * NT + tid;
    ulonglong2 o = *rpt;
    ulonglong2 p = *rsq;
    float2 ox = *rx;
    SPT[0] = add2(SPT[0], fma2(o.x, M1, hPT[0]));
    SPT[1] = add2(SPT[1], fma2(o.y, M1, hPT[1]));
    SSQ[0] = add2(SSQ[0], fma2(p.x, M1, hSQ[0]));
    SSQ[1] = add2(SSQ[1], fma2(p.y, M1, hSQ[1]));
    SX[0] += hX[0] - ox.x;
    SX[1] += hX[1] - ox.y;
    *rpt = make_ulonglong2(hPT[0], hPT[1]);
    *rsq = make_ulonglong2(hSQ[0], hSQ[1]);
    *rx  = make_float2(hX[0], hX[1]);
    if (emit) {
#pragma unroll
        for (int c = 0; c < 2; c++) {
            u64 m   = mul2(SPT[c], INV2);    // (mu_x, mu_y)
            u64 e   = mul2(SSQ[c], INV2);    // (E[x^2], E[y^2])
            u64 msq = mul2(m, m);            // (mu_x^2, mu_y^2)
            float2 mf = up2(m), ef = up2(e), ms = up2(msq);
            float exy = SX[c] * inv;
            float m12 = mf.x * mf.y;
            float num = fmaf(2.f, m12, 1e-4f) * fmaf(2.f, exy - m12, 9e-4f);
            float den = (ms.x + ms.y + 1e-4f)
                      * ((ef.x - ms.x) + (ef.y - ms.y) + 9e-4f);
            acc += __saturatef(__fdividef(num, den));
        }
    }
}

__global__ __launch_bounds__(NT, 1)
void ssim_main_kernel(const float* __restrict__ pred, const float* __restrict__ targ)
{
    extern __shared__ char sm[];
    float2* rowbuf = (float2*)(sm + OF_ROW);   // [4][RS2] interleaved (p,t)
    float*  red    = (float*)(sm + OF_RED);

    const int tid   = threadIdx.x;
    const int bid   = blockIdx.x;
    const int img   = bid / NSTRIP;
    const int strip = bid - img * NSTRIP;
    const int r0    = strip * STRIPH;
    const int r1    = min(HEIGHT, r0 + STRIPH);
    const int yend  = r1 + PADR;
    const int emit0 = r0 + PADR;

    const float* __restrict__ P = pred + (size_t)img * (WIDTH * HEIGHT);
    const float* __restrict__ T = targ + (size_t)img * (WIDTH * HEIGHT);
    const int x0 = tid * 2;

    const u64 M1   = pk2(-1.f, -1.f);
    const float inv = 1.f / 121.f;
    const u64 INV2 = pk2(inv, inv);

    // zero ring (per-thread private slots; no sync needed)
    {
        ulonglong2 z2 = make_ulonglong2(0ull, 0ull);
#pragma unroll
        for (int s = 0; s < 11; s++) {
            ((ulonglong2*)(sm + OF_PT))[s * NT + tid] = z2;
            ((ulonglong2*)(sm + OF_SQ))[s * NT + tid] = z2;
            ((float2*)(sm + OF_X))[s * NT + tid] = make_float2(0.f, 0.f);
        }
    }
    // zero pads of 4 row buffers: idx 3..7 (x=-5..-1) and 520..524 (x=512..516)
    if (tid < 40) {
        int r = tid / 10, k = tid % 10;
        int idx = (k < 5) ? (3 + k) : (520 + (k - 5));
        rowbuf[r * RS2 + idx] = make_float2(0.f, 0.f);
    }

    u64 SPT[2] = {0, 0}, SSQ[2] = {0, 0};
    float SX[2] = {0.f, 0.f};
    float acc = 0.f;
    int slot = 0;

    const int start = r0 - PADR;
    float2 cp0 = {}, ct0 = {}, cp1 = {}, ct1 = {};
    if (start >= 0 && start < HEIGHT) {
        cp0 = *(const float2*)(P + (size_t)start * WIDTH + x0);
        ct0 = *(const float2*)(T + (size_t)start * WIDTH + x0);
    }
    if (start + 1 >= 0 && start + 1 < HEIGHT) {
        cp1 = *(const float2*)(P + (size_t)(start + 1) * WIDTH + x0);
        ct1 = *(const float2*)(T + (size_t)(start + 1) * WIDTH + x0);
    }

    __syncthreads();   // pads visible

    for (int base = start; base < yend; base += 2) {
        const int pb = (base >> 1) & 1;
        float2* rA = rowbuf + (pb * 2 + 0) * RS2;
        float2* rB = rowbuf + (pb * 2 + 1) * RS2;
        const bool vA = (base >= 0) && (base < HEIGHT);
        const bool vB = (base + 1 >= 0) && (base + 1 < HEIGHT);

        u64 oA0 = 0, oA1 = 0, oB0 = 0, oB1 = 0;
        if (vA) {
            oA0 = pk2(cp0.x, ct0.x); oA1 = pk2(cp0.y, ct0.y);
            *(float4*)(rA + x0 + 8) = make_float4(cp0.x, ct0.x, cp0.y, ct0.y);
        }
        if (vB) {
            oB0 = pk2(cp1.x, ct1.x); oB1 = pk2(cp1.y, ct1.y);
            *(float4*)(rB + x0 + 8) = make_float4(cp1.x, ct1.x, cp1.y, ct1.y);
        }
        // prefetch next row pair (hidden behind this pair's compute)
        {
            int yn0 = base + 2, yn1 = base + 3;
            if (yn0 >= 0 && yn0 < HEIGHT) {
                cp0 = *(const float2*)(P + (size_t)yn0 * WIDTH + x0);
                ct0 = *(const float2*)(T + (size_t)yn0 * WIDTH + x0);
            }
            if (yn1 >= 0 && yn1 < HEIGHT) {
                cp1 = *(const float2*)(P + (size_t)yn1 * WIDTH + x0);
                ct1 = *(const float2*)(T + (size_t)yn1 * WIDTH + x0);
            }
        }
        __syncthreads();   // row pair visible (alternating pair-buffers)

        u64 hPT[2], hSQ[2]; float hX[2];
        if (vA) {
            hwin2(rA, x0, oA0, oA1, M1, hPT, hSQ, hX);
        } else {
            hPT[0] = hPT[1] = 0; hSQ[0] = hSQ[1] = 0; hX[0] = hX[1] = 0.f;
        }
        vrow2(sm, slot, tid, hPT, hSQ, hX, SPT, SSQ, SX, M1, INV2, inv,
              base >= emit0, acc);

        int slotB = slot + 1; if (slotB == 11) slotB = 0;
        if (vB) {
            hwin2(rB, x0, oB0, oB1, M1, hPT, hSQ, hX);
        } else {
            hPT[0] = hPT[1] = 0; hSQ[0] = hSQ[1] = 0; hX[0] = hX[1] = 0.f;
        }
        vrow2(sm, slotB, tid, hPT, hSQ, hX, SPT, SSQ, SX, M1, INV2, inv,
              (base + 1 >= emit0) && (base + 1 < yend), acc);

        slot += 2; if (slot >= 11) slot -= 11;
    }

    // deterministic block reduction
    red[tid] = acc;
    __syncthreads();
#pragma unroll
    for (int s = NT / 2; s > 0; s >>= 1) {
        if (tid < s) red[tid] += red[tid + s];
        __syncthreads();
    }
    if (tid == 0) g_partials[bid] = red[0];
}

__global__ void ssim_finalize_kernel(float* __restrict__ out) {
    const int i = threadIdx.x;
    if (i < 16) {
        float s = 0.f;
#pragma unroll
        for (int j = 0; j < 3 * NSTRIP; j++) s += g_partials[i * (3 * NSTRIP) + j];
        out[i] = 1.f - s * (1.f / (3.f * 512.f * 512.f));
    }
}

extern "C" void kernel_launch(void* const* d_in, const int* in_sizes, int n_in,
                              void* d_out, int out_size) {
    const float* pred = (const float*)d_in[0];
    const float* targ = (const float*)d_in[1];
    cudaFuncSetAttribute(ssim_main_kernel,
                         cudaFuncAttributeMaxDynamicSharedMemorySize, SMEM_SZ);
    ssim_main_kernel<<<NBLOCKS, NT, SMEM_SZ>>>(pred, targ);
    ssim_finalize_kernel<<<1, 32>>>((float*)d_out);
}

// round 6
// speedup vs baseline: 1.6640x; 1.0348x over previous
#include <cuda_runtime.h>

// SSIM loss, fused single pass, f32x2-packed, NT=256, 2 cols/thread.
// Vertical 11-row sliding-sum ring held in REGISTERS (22-row unrolled inner
// loop -> static ring slots). smem holds only double-buffered row pairs.
// Finalize folded into main kernel via last-block pattern.
// pred/target: (16,3,512,512) fp32. out: 16 fp32 (1 - mean ssim per sample).

#define WIDTH   512
#define HEIGHT  512
#define PADR    5
#define NT      256
#define NSTRIP  3
#define STRIPH  171
#define RS2     528
#define NBLOCKS (48 * NSTRIP)

// SSIM constants with the 1/121 normalization folded out (121^4 cancels):
// K1 = C1*121^2, K2 = C2*121^2
#define K1f 1.4641f
#define K2f 13.1769f

typedef unsigned long long u64;

__device__ float g_partials[NBLOCKS];
__device__ unsigned int g_count;

__device__ __forceinline__ u64 pk2(float a, float b) {
    u64 r; asm("mov.b64 %0,{%1,%2};" : "=l"(r) : "f"(a), "f"(b)); return r;
}
__device__ __forceinline__ float2 up2(u64 a) {
    float2 r; asm("mov.b64 {%0,%1},%2;" : "=f"(r.x), "=f"(r.y) : "l"(a)); return r;
}
__device__ __forceinline__ u64 add2(u64 a, u64 b) {
    u64 r; asm("add.rn.f32x2 %0,%1,%2;" : "=l"(r) : "l"(a), "l"(b)); return r;
}
__device__ __forceinline__ u64 mul2(u64 a, u64 b) {
    u64 r; asm("mul.rn.f32x2 %0,%1,%2;" : "=l"(r) : "l"(a), "l"(b)); return r;
}
__device__ __forceinline__ u64 fma2(u64 a, u64 b, u64 c) {
    u64 r; asm("fma.rn.f32x2 %0,%1,%2,%3;" : "=l"(r) : "l"(a), "l"(b), "l"(c)); return r;
}

// Horizontal 11-tap windows for 2 output columns (x0, x0+1).
// Window covers buffer idx [x0+3, x0+14]; own0/own1 = idx x0+8, x0+9 in regs.
__device__ __forceinline__ void hwin2(const float2* __restrict__ row, int x0,
                                      u64 own0, u64 own1, u64 M1,
                                      u64 hPT[2], u64 hSQ[2], float hX[2])
{
    u64 pt[12];
    {
        ulonglong2 a = *(const ulonglong2*)(row + x0 + 2);
        ulonglong2 b = *(const ulonglong2*)(row + x0 + 4);
        ulonglong2 c = *(const ulonglong2*)(row + x0 + 6);
        pt[0] = a.y; pt[1] = b.x; pt[2] = b.y; pt[3] = c.x; pt[4] = c.y;
    }
    pt[5] = own0; pt[6] = own1;
    {
        ulonglong2 d = *(const ulonglong2*)(row + x0 + 10);
        ulonglong2 e = *(const ulonglong2*)(row + x0 + 12);
        ulonglong2 f = *(const ulonglong2*)(row + x0 + 14);
        pt[7] = d.x; pt[8] = d.y; pt[9] = e.x; pt[10] = e.y; pt[11] = f.x;
    }

    u64 s = pt[0];
    u64 q = mul2(pt[0], pt[0]);
    float2 f0 = up2(pt[0]);
    float x = f0.x * f0.y;
#pragma unroll
    for (int k = 1; k < 11; k++) {
        s = add2(s, pt[k]);
        q = fma2(pt[k], pt[k], q);
        float2 g = up2(pt[k]);
        x = fmaf(g.x, g.y, x);
    }
    hPT[0] = s; hSQ[0] = q; hX[0] = x;
    // slide by one
    s = add2(s, pt[11]);
    s = fma2(pt[0], M1, s);
    q = fma2(pt[11], pt[11], q);
    q = fma2(pt[0], mul2(pt[0], M1), q);
    float2 fn = up2(pt[11]);
    x = fmaf(fn.x, fn.y, x);
    x = fmaf(-f0.x, f0.y, x);
    hPT[1] = s; hSQ[1] = q; hX[1] = x;
}

// SSIM emit for 2 columns from raw window sums (121-normalization folded out).
__device__ __forceinline__ void emit2(const u64 SPT[2], const u64 SSQ[2],
                                      const float SX[2], float& acc)
{
#pragma unroll
    for (int c = 0; c < 2; c++) {
        float2 mf = up2(SPT[c]);            // (Mx, My) = raw sums
        float2 qf = up2(SSQ[c]);            // (Qx, Qy) = raw square sums
        float2 ms = up2(mul2(SPT[c], SPT[c]));   // (Mx^2, My^2)
        float m12 = mf.x * mf.y;
        float a   = fmaf(2.f, m12, K1f);
        float b   = fmaf(242.f, SX[c], fmaf(-2.f, m12, K2f));
        float num = a * b;
        float u   = ms.x + ms.y;
        float d1  = u + K1f;
        float d2  = fmaf(121.f, qf.x + qf.y, K2f - u);
        acc += __saturatef(__fdividef(num, d1 * d2));
    }
}

__global__ __launch_bounds__(NT, 1)
void ssim_main_kernel(const float* __restrict__ pred, const float* __restrict__ targ,
                      float* __restrict__ out)
{
    __shared__ float2 rowbuf[4 * RS2];     // 2 pair-buffers x 2 rows, (p,t) interleaved
    __shared__ float  red[NT];
    __shared__ int    s_last;

    const int tid   = threadIdx.x;
    const int bid   = blockIdx.x;
    const int img   = bid / NSTRIP;
    const int strip = bid - img * NSTRIP;
    const int r0    = strip * STRIPH;
    const int r1    = min(HEIGHT, r0 + STRIPH);
    const int yend  = r1 + PADR;
    const int emit0 = r0 + PADR;
    const int start = r0 - PADR;

    const float* __restrict__ P = pred + (size_t)img * (WIDTH * HEIGHT);
    const float* __restrict__ T = targ + (size_t)img * (WIDTH * HEIGHT);
    const int x0 = tid * 2;

    const u64 M1 = pk2(-1.f, -1.f);

    // vertical ring in REGISTERS (static slots via full unroll below)
    u64 rPT[11][2], rSQ[11][2];
    float rX[11][2];
#pragma unroll
    for (int s = 0; s < 11; s++) {
        rPT[s][0] = 0; rPT[s][1] = 0;
        rSQ[s][0] = 0; rSQ[s][1] = 0;
        rX[s][0] = 0.f; rX[s][1] = 0.f;
    }

    // zero pads of 4 row buffers: idx 3..7 (x=-5..-1) and 520..524 (x=512..516)
    if (tid < 40) {
        int r = tid / 10, k = tid % 10;
        int idx = (k < 5) ? (3 + k) : (520 + (k - 5));
        rowbuf[r * RS2 + idx] = make_float2(0.f, 0.f);
    }

    u64 SPT[2] = {0, 0}, SSQ[2] = {0, 0};
    float SX[2] = {0.f, 0.f};
    float acc = 0.f;

    float2 cp0 = {}, ct0 = {}, cp1 = {}, ct1 = {};
    if (start >= 0) {
        cp0 = *(const float2*)(P + (size_t)start * WIDTH + x0);
        ct0 = *(const float2*)(T + (size_t)start * WIDTH + x0);
    }
    if (start + 1 >= 0) {
        cp1 = *(const float2*)(P + (size_t)(start + 1) * WIDTH + x0);
        ct1 = *(const float2*)(T + (size_t)(start + 1) * WIDTH + x0);
    }

    __syncthreads();   // pads visible

    int kpar = 0;
    for (int y0 = start; y0 < yend; y0 += 22, kpar ^= 1) {
#pragma unroll
        for (int p = 0; p < 11; p++) {
            const int base = y0 + 2 * p;
            if (base < yend) {                      // uniform across block
                const int pb = kpar ^ (p & 1);
                float2* rA = rowbuf + (pb * 2 + 0) * RS2;
                float2* rB = rowbuf + (pb * 2 + 1) * RS2;
                const bool vA = (base >= 0) && (base < HEIGHT);
                const bool vB = (base + 1 >= 0) && (base + 1 < HEIGHT);

                u64 oA0 = 0, oA1 = 0, oB0 = 0, oB1 = 0;
                if (vA) {
                    oA0 = pk2(cp0.x, ct0.x); oA1 = pk2(cp0.y, ct0.y);
                    *(float4*)(rA + x0 + 8) = make_float4(cp0.x, ct0.x, cp0.y, ct0.y);
                }
                if (vB) {
                    oB0 = pk2(cp1.x, ct1.x); oB1 = pk2(cp1.y, ct1.y);
                    *(float4*)(rB + x0 + 8) = make_float4(cp1.x, ct1.x, cp1.y, ct1.y);
                }
                // prefetch next row pair
                {
                    int yn0 = base + 2, yn1 = base + 3;
                    if (yn0 >= 0 && yn0 < HEIGHT) {
                        cp0 = *(const float2*)(P + (size_t)yn0 * WIDTH + x0);
                        ct0 = *(const float2*)(T + (size_t)yn0 * WIDTH + x0);
                    }
                    if (yn1 >= 0 && yn1 < HEIGHT) {
                        cp1 = *(const float2*)(P + (size_t)yn1 * WIDTH + x0);
                        ct1 = *(const float2*)(T + (size_t)yn1 * WIDTH + x0);
                    }
                }
                __syncthreads();   // row pair visible (alternating pair-buffers)

                u64 hPT[2], hSQ[2]; float hX[2];
                // ---- row A, ring slot (2p)%11 (static after unroll) ----
                if (vA) {
                    hwin2(rA, x0, oA0, oA1, M1, hPT, hSQ, hX);
                } else {
                    hPT[0] = hPT[1] = 0; hSQ[0] = hSQ[1] = 0; hX[0] = hX[1] = 0.f;
                }
                {
                    const int sA = (2 * p) % 11;
#pragma unroll
                    for (int c = 0; c < 2; c++) {
                        SPT[c] = add2(SPT[c], fma2(rPT[sA][c], M1, hPT[c]));
                        SSQ[c] = add2(SSQ[c], fma2(rSQ[sA][c], M1, hSQ[c]));
                        SX[c] += hX[c] - rX[sA][c];
                        rPT[sA][c] = hPT[c]; rSQ[sA][c] = hSQ[c]; rX[sA][c] = hX[c];
                    }
                }
                if (base >= emit0) emit2(SPT, SSQ, SX, acc);

                // ---- row B, ring slot (2p+1)%11 ----
                if (vB) {
                    hwin2(rB, x0, oB0, oB1, M1, hPT, hSQ, hX);
                } else {
                    hPT[0] = hPT[1] = 0; hSQ[0] = hSQ[1] = 0; hX[0] = hX[1] = 0.f;
                }
                {
                    const int sB = (2 * p + 1) % 11;
#pragma unroll
                    for (int c = 0; c < 2; c++) {
                        SPT[c] = add2(SPT[c], fma2(rPT[sB][c], M1, hPT[c]));
                        SSQ[c] = add2(SSQ[c], fma2(rSQ[sB][c], M1, hSQ[c]));
                        SX[c] += hX[c] - rX[sB][c];
                        rPT[sB][c] = hPT[c]; rSQ[sB][c] = hSQ[c]; rX[sB][c] = hX[c];
                    }
                }
                if (base + 1 >= emit0 && base + 1 < yend) emit2(SPT, SSQ, SX, acc);
            }
        }
    }

    // deterministic block reduction
    red[tid] = acc;
    __syncthreads();
#pragma unroll
    for (int s = NT / 2; s > 0; s >>= 1) {
        if (tid < s) red[tid] += red[tid + s];
        __syncthreads();
    }
    if (tid == 0) {
        g_partials[bid] = red[0];
        __threadfence();
        unsigned int c = atomicAdd(&g_count, 1);
        s_last = (c == NBLOCKS - 1);
    }
    __syncthreads();
    if (s_last) {
        if (tid < 16) {
            float s = 0.f;
#pragma unroll
            for (int j = 0; j < 3 * NSTRIP; j++)
                s += __ldcg(&g_partials[tid * (3 * NSTRIP) + j]);
            out[tid] = 1.f - s * (1.f / (3.f * 512.f * 512.f));
        }
        if (tid == 0) g_count = 0;   // reset for next graph replay
    }
}

extern "C" void kernel_launch(void* const* d_in, const int* in_sizes, int n_in,
                              void* d_out, int out_size) {
    const float* pred = (const float*)d_in[0];
    const float* targ = (const float*)d_in[1];
    ssim_main_kernel<<<NBLOCKS, NT>>>(pred, targ, (float*)d_out);
}

// round 7
// speedup vs baseline: 2.2164x; 1.3320x over previous
#include <cuda_runtime.h>

// SSIM loss, fused single pass, f32x2-packed, NT=256, 2 cols/thread,
// 6 strips -> grid 288 -> 2 CTAs/SM -> 4 warps/SMSP.
// PT ring in registers (static slots); SQ and X rings in smem (fits 128 regs).
// Finalize folded in via last-block pattern.
// pred/target: (16,3,512,512) fp32. out: 16 fp32 (1 - mean ssim per sample).

#define WIDTH   512
#define HEIGHT  512
#define PADR    5
#define NT      256
#define NSTRIP  6
#define STRIPH  86
#define RS2     528
#define NBLOCKS (48 * NSTRIP)

// smem byte offsets (dynamic)
#define OF_SQ   0              // 11*256*16 = 45056
#define OF_X    45056          // 11*256*8  = 22528
#define OF_ROW  67584          // 4*528*8   = 16896
#define OF_RED  84480          // 256*4
#define SMEM_SZ 85504

// SSIM constants with the 1/121 normalization folded out (121^4 cancels):
#define K1f 1.4641f
#define K2f 13.1769f

typedef unsigned long long u64;

__device__ float g_partials[NBLOCKS];
__device__ unsigned int g_count;

__device__ __forceinline__ u64 pk2(float a, float b) {
    u64 r; asm("mov.b64 %0,{%1,%2};" : "=l"(r) : "f"(a), "f"(b)); return r;
}
__device__ __forceinline__ float2 up2(u64 a) {
    float2 r; asm("mov.b64 {%0,%1},%2;" : "=f"(r.x), "=f"(r.y) : "l"(a)); return r;
}
__device__ __forceinline__ u64 add2(u64 a, u64 b) {
    u64 r; asm("add.rn.f32x2 %0,%1,%2;" : "=l"(r) : "l"(a), "l"(b)); return r;
}
__device__ __forceinline__ u64 mul2(u64 a, u64 b) {
    u64 r; asm("mul.rn.f32x2 %0,%1,%2;" : "=l"(r) : "l"(a), "l"(b)); return r;
}
__device__ __forceinline__ u64 fma2(u64 a, u64 b, u64 c) {
    u64 r; asm("fma.rn.f32x2 %0,%1,%2,%3;" : "=l"(r) : "l"(a), "l"(b), "l"(c)); return r;
}

// Horizontal 11-tap windows for 2 output columns (x0, x0+1).
__device__ __forceinline__ void hwin2(const float2* __restrict__ row, int x0,
                                      u64 own0, u64 own1, u64 M1,
                                      u64 hPT[2], u64 hSQ[2], float hX[2])
{
    u64 pt[12];
    {
        ulonglong2 a = *(const ulonglong2*)(row + x0 + 2);
        ulonglong2 b = *(const ulonglong2*)(row + x0 + 4);
        ulonglong2 c = *(const ulonglong2*)(row + x0 + 6);
        pt[0] = a.y; pt[1] = b.x; pt[2] = b.y; pt[3] = c.x; pt[4] = c.y;
    }
    pt[5] = own0; pt[6] = own1;
    {
        ulonglong2 d = *(const ulonglong2*)(row + x0 + 10);
        ulonglong2 e = *(const ulonglong2*)(row + x0 + 12);
        ulonglong2 f = *(const ulonglong2*)(row + x0 + 14);
        pt[7] = d.x; pt[8] = d.y; pt[9] = e.x; pt[10] = e.y; pt[11] = f.x;
    }

    u64 s = pt[0];
    u64 q = mul2(pt[0], pt[0]);
    float2 f0 = up2(pt[0]);
    float x = f0.x * f0.y;
#pragma unroll
    for (int k = 1; k < 11; k++) {
        s = add2(s, pt[k]);
        q = fma2(pt[k], pt[k], q);
        float2 g = up2(pt[k]);
        x = fmaf(g.x, g.y, x);
    }
    hPT[0] = s; hSQ[0] = q; hX[0] = x;
    // slide by one
    s = add2(s, pt[11]);
    s = fma2(pt[0], M1, s);
    q = fma2(pt[11], pt[11], q);
    q = fma2(pt[0], mul2(pt[0], M1), q);
    float2 fn = up2(pt[11]);
    x = fmaf(fn.x, fn.y, x);
    x = fmaf(-f0.x, f0.y, x);
    hPT[1] = s; hSQ[1] = q; hX[1] = x;
}

// SSIM emit for 2 columns from raw window sums (121-normalization folded out).
__device__ __forceinline__ void emit2(const u64 SPT[2], const u64 SSQ[2],
                                      const float SX[2], float& acc)
{
#pragma unroll
    for (int c = 0; c < 2; c++) {
        float2 mf = up2(SPT[c]);
        float2 qf = up2(SSQ[c]);
        float2 ms = up2(mul2(SPT[c], SPT[c]));
        float m12 = mf.x * mf.y;
        float a   = fmaf(2.f, m12, K1f);
        float b   = fmaf(242.f, SX[c], fmaf(-2.f, m12, K2f));
        float num = a * b;
        float u   = ms.x + ms.y;
        float d1  = u + K1f;
        float d2  = fmaf(121.f, qf.x + qf.y, K2f - u);
        acc += __saturatef(__fdividef(num, d1 * d2));
    }
}

__global__ __launch_bounds__(NT, 2)
void ssim_main_kernel(const float* __restrict__ pred, const float* __restrict__ targ,
                      float* __restrict__ out)
{
    extern __shared__ char sm[];
    float2* rowbuf = (float2*)(sm + OF_ROW);
    float*  red    = (float*)(sm + OF_RED);
    __shared__ int s_last;

    const int tid   = threadIdx.x;
    const int bid   = blockIdx.x;
    const int img   = bid / NSTRIP;
    const int strip = bid - img * NSTRIP;
    const int r0    = strip * STRIPH;
    const int r1    = min(HEIGHT, r0 + STRIPH);
    const int yend  = r1 + PADR;
    const int emit0 = r0 + PADR;
    const int start = r0 - PADR;

    const float* __restrict__ P = pred + (size_t)img * (WIDTH * HEIGHT);
    const float* __restrict__ T = targ + (size_t)img * (WIDTH * HEIGHT);
    const int x0 = tid * 2;

    const u64 M1 = pk2(-1.f, -1.f);

    // PT ring in registers (static slots via full unroll below)
    u64 rPT[11][2];
#pragma unroll
    for (int s = 0; s < 11; s++) { rPT[s][0] = 0; rPT[s][1] = 0; }

    // per-thread smem ring bases (slot offsets are compile-time constants)
    ulonglong2* sqr = (ulonglong2*)(sm + OF_SQ) + tid;
    float2*     xr  = (float2*)(sm + OF_X) + tid;
    {
        ulonglong2 z2 = make_ulonglong2(0ull, 0ull);
#pragma unroll
        for (int s = 0; s < 11; s++) {
            sqr[s * NT] = z2;
            xr[s * NT]  = make_float2(0.f, 0.f);
        }
    }
    // zero pads of 4 row buffers: idx 3..7 (x=-5..-1) and 520..524 (x=512..516)
    if (tid < 40) {
        int r = tid / 10, k = tid % 10;
        int idx = (k < 5) ? (3 + k) : (520 + (k - 5));
        rowbuf[r * RS2 + idx] = make_float2(0.f, 0.f);
    }

    u64 SPT[2] = {0, 0}, SSQ[2] = {0, 0};
    float SX[2] = {0.f, 0.f};
    float acc = 0.f;

    float2 cp0 = {}, ct0 = {}, cp1 = {}, ct1 = {};
    if (start >= 0) {
        cp0 = *(const float2*)(P + (size_t)start * WIDTH + x0);
        ct0 = *(const float2*)(T + (size_t)start * WIDTH + x0);
    }
    if (start + 1 >= 0) {
        cp1 = *(const float2*)(P + (size_t)(start + 1) * WIDTH + x0);
        ct1 = *(const float2*)(T + (size_t)(start + 1) * WIDTH + x0);
    }

    __syncthreads();   // pads + zeroed rings visible

    int kpar = 0;
    for (int y0 = start; y0 < yend; y0 += 22, kpar ^= 1) {
#pragma unroll
        for (int p = 0; p < 11; p++) {
            const int base = y0 + 2 * p;
            if (base < yend) {                      // uniform across block
                const int pb = kpar ^ (p & 1);
                float2* rA = rowbuf + (pb * 2 + 0) * RS2;
                float2* rB = rowbuf + (pb * 2 + 1) * RS2;
                const bool vA = (base >= 0) && (base < HEIGHT);
                const bool vB = (base + 1 >= 0) && (base + 1 < HEIGHT);

                u64 oA0 = 0, oA1 = 0, oB0 = 0, oB1 = 0;
                if (vA) {
                    oA0 = pk2(cp0.x, ct0.x); oA1 = pk2(cp0.y, ct0.y);
                    *(float4*)(rA + x0 + 8) = make_float4(cp0.x, ct0.x, cp0.y, ct0.y);
                }
                if (vB) {
                    oB0 = pk2(cp1.x, ct1.x); oB1 = pk2(cp1.y, ct1.y);
                    *(float4*)(rB + x0 + 8) = make_float4(cp1.x, ct1.x, cp1.y, ct1.y);
                }
                // prefetch next row pair
                {
                    int yn0 = base + 2, yn1 = base + 3;
                    if (yn0 >= 0 && yn0 < HEIGHT) {
                        cp0 = *(const float2*)(P + (size_t)yn0 * WIDTH + x0);
                        ct0 = *(const float2*)(T + (size_t)yn0 * WIDTH + x0);
                    }
                    if (yn1 >= 0 && yn1 < HEIGHT) {
                        cp1 = *(const float2*)(P + (size_t)yn1 * WIDTH + x0);
                        ct1 = *(const float2*)(T + (size_t)yn1 * WIDTH + x0);
                    }
                }
                __syncthreads();   // row pair visible (alternating pair-buffers)

                u64 hPT[2], hSQ[2]; float hX[2];
                // ---- row A, ring slot (2p)%11 (compile-time constant) ----
                if (vA) {
                    hwin2(rA, x0, oA0, oA1, M1, hPT, hSQ, hX);
                } else {
                    hPT[0] = hPT[1] = 0; hSQ[0] = hSQ[1] = 0; hX[0] = hX[1] = 0.f;
                }
                {
                    const int sA = (2 * p) % 11;
                    ulonglong2 q = sqr[sA * NT];
                    float2    ox = xr[sA * NT];
                    SPT[0] = add2(SPT[0], fma2(rPT[sA][0], M1, hPT[0]));
                    SPT[1] = add2(SPT[1], fma2(rPT[sA][1], M1, hPT[1]));
                    SSQ[0] = add2(SSQ[0], fma2(q.x, M1, hSQ[0]));
                    SSQ[1] = add2(SSQ[1], fma2(q.y, M1, hSQ[1]));
                    SX[0] += hX[0] - ox.x;
                    SX[1] += hX[1] - ox.y;
                    rPT[sA][0] = hPT[0]; rPT[sA][1] = hPT[1];
                    sqr[sA * NT] = make_ulonglong2(hSQ[0], hSQ[1]);
                    xr[sA * NT]  = make_float2(hX[0], hX[1]);
                }
                if (base >= emit0) emit2(SPT, SSQ, SX, acc);

                // ---- row B, ring slot (2p+1)%11 ----
                if (vB) {
                    hwin2(rB, x0, oB0, oB1, M1, hPT, hSQ, hX);
                } else {
                    hPT[0] = hPT[1] = 0; hSQ[0] = hSQ[1] = 0; hX[0] = hX[1] = 0.f;
                }
                {
                    const int sB = (2 * p + 1) % 11;
                    ulonglong2 q = sqr[sB * NT];
                    float2    ox = xr[sB * NT];
                    SPT[0] = add2(SPT[0], fma2(rPT[sB][0], M1, hPT[0]));
                    SPT[1] = add2(SPT[1], fma2(rPT[sB][1], M1, hPT[1]));
                    SSQ[0] = add2(SSQ[0], fma2(q.x, M1, hSQ[0]));
                    SSQ[1] = add2(SSQ[1], fma2(q.y, M1, hSQ[1]));
                    SX[0] += hX[0] - ox.x;
                    SX[1] += hX[1] - ox.y;
                    rPT[sB][0] = hPT[0]; rPT[sB][1] = hPT[1];
                    sqr[sB * NT] = make_ulonglong2(hSQ[0], hSQ[1]);
                    xr[sB * NT]  = make_float2(hX[0], hX[1]);
                }
                if (base + 1 >= emit0 && base + 1 < yend) emit2(SPT, SSQ, SX, acc);
            }
        }
    }

    // deterministic block reduction
    red[tid] = acc;
    __syncthreads();
#pragma unroll
    for (int s = NT / 2; s > 0; s >>= 1) {
        if (tid < s) red[tid] += red[tid + s];
        __syncthreads();
    }
    if (tid == 0) {
        g_partials[bid] = red[0];
        __threadfence();
        unsigned int c = atomicAdd(&g_count, 1);
        s_last = (c == NBLOCKS - 1);
    }
    __syncthreads();
    if (s_last) {
        if (tid < 16) {
            float s = 0.f;
#pragma unroll
            for (int j = 0; j < 3 * NSTRIP; j++)
                s += __ldcg(&g_partials[tid * (3 * NSTRIP) + j]);
            out[tid] = 1.f - s * (1.f / (3.f * 512.f * 512.f));
        }
        if (tid == 0) g_count = 0;   // reset for next graph replay
    }
}

extern "C" void kernel_launch(void* const* d_in, const int* in_sizes, int n_in,
                              void* d_out, int out_size) {
    const float* pred = (const float*)d_in[0];
    const float* targ = (const float*)d_in[1];
    cudaFuncSetAttribute(ssim_main_kernel,
                         cudaFuncAttributeMaxDynamicSharedMemorySize, SMEM_SZ);
    ssim_main_kernel<<<NBLOCKS, NT, SMEM_SZ>>>(pred, targ, (float*)d_out);
}

// round 9
// speedup vs baseline: 2.3031x; 1.0391x over previous
#include <cuda_runtime.h>

// SSIM loss, fused single pass. (u,v)=(p+t,p-t) rotation: all 5 window stats
// from TWO packed f32x2 chains (sum, sum-of-squares). NT=256, 2 cols/thread,
// 6 strips -> grid 288 -> 2 CTAs/SM -> 4 warps/SMSP.
// UV ring in registers (static slots); Q ring in smem. Last-block finalize.
// pred/target: (16,3,512,512) fp32. out: 16 fp32 (1 - mean ssim per sample).

#define WIDTH   512
#define HEIGHT  512
#define PADR    5
#define NT      256
#define NSTRIP  6
#define STRIPH  86
#define RS2     528
#define NBLOCKS (48 * NSTRIP)

// smem byte offsets (dynamic)
#define OF_Q    0              // 11*256*16 = 45056
#define OF_ROW  45056          // 4*528*8   = 16896
#define OF_RED  61952          // 256*4
#define SMEM_SZ 62976

// SSIM constants with 1/121 folded out: K1=C1*121^2, K2=C2*121^2
#define K1f 1.4641f
#define K2f 13.1769f

typedef unsigned long long u64;

__device__ float g_partials[NBLOCKS];
__device__ unsigned int g_count;

__device__ __forceinline__ u64 pk2(float a, float b) {
    u64 r; asm("mov.b64 %0,{%1,%2};" : "=l"(r) : "f"(a), "f"(b)); return r;
}
__device__ __forceinline__ float2 up2(u64 a) {
    float2 r; asm("mov.b64 {%0,%1},%2;" : "=f"(r.x), "=f"(r.y) : "l"(a)); return r;
}
__device__ __forceinline__ u64 add2(u64 a, u64 b) {
    u64 r; asm("add.rn.f32x2 %0,%1,%2;" : "=l"(r) : "l"(a), "l"(b)); return r;
}
__device__ __forceinline__ u64 mul2(u64 a, u64 b) {
    u64 r; asm("mul.rn.f32x2 %0,%1,%2;" : "=l"(r) : "l"(a), "l"(b)); return r;
}
__device__ __forceinline__ u64 fma2(u64 a, u64 b, u64 c) {
    u64 r; asm("fma.rn.f32x2 %0,%1,%2,%3;" : "=l"(r) : "l"(a), "l"(b), "l"(c)); return r;
}

// Horizontal 11-tap windows (2 chains) for 2 output columns (x0, x0+1).
// Row buffer holds packed (u,v) per col; window covers idx [x0+3, x0+14];
// own0/own1 = idx x0+8, x0+9 kept in regs.
__device__ __forceinline__ void hwin2(const float2* __restrict__ row, int x0,
                                      u64 own0, u64 own1, u64 M1,
                                      u64 hUV[2], u64 hQ[2])
{
    u64 pt[12];
    {
        ulonglong2 a = *(const ulonglong2*)(row + x0 + 2);
        ulonglong2 b = *(const ulonglong2*)(row + x0 + 4);
        ulonglong2 c = *(const ulonglong2*)(row + x0 + 6);
        pt[0] = a.y; pt[1] = b.x; pt[2] = b.y; pt[3] = c.x; pt[4] = c.y;
    }
    pt[5] = own0; pt[6] = own1;
    {
        ulonglong2 d = *(const ulonglong2*)(row + x0 + 10);
        ulonglong2 e = *(const ulonglong2*)(row + x0 + 12);
        ulonglong2 f = *(const ulonglong2*)(row + x0 + 14);
        pt[7] = d.x; pt[8] = d.y; pt[9] = e.x; pt[10] = e.y; pt[11] = f.x;
    }

    u64 s = pt[0];
    u64 q = mul2(pt[0], pt[0]);
#pragma unroll
    for (int k = 1; k < 11; k++) {
        s = add2(s, pt[k]);
        q = fma2(pt[k], pt[k], q);
    }
    hUV[0] = s; hQ[0] = q;
    // slide by one
    s = add2(s, pt[11]);
    s = fma2(pt[0], M1, s);
    q = fma2(pt[11], pt[11], q);
    q = fma2(pt[0], mul2(pt[0], M1), q);
    hUV[1] = s; hQ[1] = q;
}

// SSIM emit for 2 columns from raw (u,v) window sums.
//  Su2-Sv2 = 4*Mx*My ; Su2+Sv2 = 2*(Mx^2+My^2)
//  Qu-Qv   = 4*S(pt) ; Qu+Qv   = 2*(S(p^2)+S(t^2))
__device__ __forceinline__ void emit2(const u64 SUV[2], const u64 SQ2[2], float& acc)
{
#pragma unroll
    for (int c = 0; c < 2; c++) {
        float2 qf = up2(SQ2[c]);                 // (Qu, Qv)
        float2 s2 = up2(mul2(SUV[c], SUV[c]));   // (Su^2, Sv^2)
        float A = s2.x - s2.y;                   // 4*Mx*My
        float B = s2.x + s2.y;                   // 2*(Mx^2+My^2)
        float qd = qf.x - qf.y;                  // 4*S(pt)
        float qs = qf.x + qf.y;                  // 2*(Sp2+St2)
        float a  = fmaf(0.5f, A, K1f);           // 2*Mx*My + K1
        float b  = fmaf(60.5f, qd, fmaf(-0.5f, A, K2f));  // 242*S(pt) - 2MxMy + K2
        float d1 = fmaf(0.5f, B, K1f);
        float d2 = fmaf(60.5f, qs, fmaf(-0.5f, B, K2f));  // 121*(Sp2+St2) - (Mx^2+My^2) + K2
        acc += __saturatef(__fdividef(a * b, d1 * d2));
    }
}

__global__ __launch_bounds__(NT, 2)
void ssim_main_kernel(const float* __restrict__ pred, const float* __restrict__ targ,
                      float* __restrict__ out)
{
    extern __shared__ char sm[];
    float2* rowbuf = (float2*)(sm + OF_ROW);
    float*  red    = (float*)(sm + OF_RED);
    __shared__ int s_last;

    const int tid   = threadIdx.x;
    const int bid   = blockIdx.x;
    const int img   = bid / NSTRIP;
    const int strip = bid - img * NSTRIP;
    const int r0    = strip * STRIPH;
    const int r1    = min(HEIGHT, r0 + STRIPH);
    const int yend  = r1 + PADR;
    const int emit0 = r0 + PADR;
    const int start = r0 - PADR;

    const float* __restrict__ P = pred + (size_t)img * (WIDTH * HEIGHT);
    const float* __restrict__ T = targ + (size_t)img * (WIDTH * HEIGHT);
    const int x0 = tid * 2;

    const u64 M1 = pk2(-1.f, -1.f);

    // UV ring in registers (static slots via full unroll below)
    u64 rUV[11][2];
#pragma unroll
    for (int s = 0; s < 11; s++) { rUV[s][0] = 0; rUV[s][1] = 0; }

    // Q ring in smem (per-thread slots, compile-time offsets)
    ulonglong2* qring = (ulonglong2*)(sm + OF_Q) + tid;
    {
        ulonglong2 z2 = make_ulonglong2(0ull, 0ull);
#pragma unroll
        for (int s = 0; s < 11; s++) qring[s * NT] = z2;
    }
    // zero pads of 4 row buffers: idx 3..7 (x=-5..-1) and 520..524 (x=512..516)
    if (tid < 40) {
        int r = tid / 10, k = tid % 10;
        int idx = (k < 5) ? (3 + k) : (520 + (k - 5));
        rowbuf[r * RS2 + idx] = make_float2(0.f, 0.f);
    }

    u64 SUV[2] = {0, 0}, SQ2[2] = {0, 0};
    float acc = 0.f;

    float2 cp0 = {}, ct0 = {}, cp1 = {}, ct1 = {};
    if (start >= 0) {
        cp0 = *(const float2*)(P + (size_t)start * WIDTH + x0);
        ct0 = *(const float2*)(T + (size_t)start * WIDTH + x0);
    }
    if (start + 1 >= 0) {
        cp1 = *(const float2*)(P + (size_t)(start + 1) * WIDTH + x0);
        ct1 = *(const float2*)(T + (size_t)(start + 1) * WIDTH + x0);
    }

    __syncthreads();   // pads + zeroed ring visible

    int kpar = 0;
    for (int y0 = start; y0 < yend; y0 += 22, kpar ^= 1) {
#pragma unroll
        for (int p = 0; p < 11; p++) {
            const int base = y0 + 2 * p;
            if (base < yend) {                      // uniform across block
                const int pb = kpar ^ (p & 1);
                float2* rA = rowbuf + (pb * 2 + 0) * RS2;
                float2* rB = rowbuf + (pb * 2 + 1) * RS2;
                const bool vA = (base >= 0) && (base < HEIGHT);
                const bool vB = (base + 1 >= 0) && (base + 1 < HEIGHT);

                u64 oA0 = 0, oA1 = 0, oB0 = 0, oB1 = 0;
                if (vA) {
                    float u0 = cp0.x + ct0.x, v0 = cp0.x - ct0.x;
                    float u1 = cp0.y + ct0.y, v1 = cp0.y - ct0.y;
                    oA0 = pk2(u0, v0); oA1 = pk2(u1, v1);
                    *(float4*)(rA + x0 + 8) = make_float4(u0, v0, u1, v1);
                }
                if (vB) {
                    float u0 = cp1.x + ct1.x, v0 = cp1.x - ct1.x;
                    float u1 = cp1.y + ct1.y, v1 = cp1.y - ct1.y;
                    oB0 = pk2(u0, v0); oB1 = pk2(u1, v1);
                    *(float4*)(rB + x0 + 8) = make_float4(u0, v0, u1, v1);
                }
                // prefetch next row pair
                {
                    int yn0 = base + 2, yn1 = base + 3;
                    if (yn0 >= 0 && yn0 < HEIGHT) {
                        cp0 = *(const float2*)(P + (size_t)yn0 * WIDTH + x0);
                        ct0 = *(const float2*)(T + (size_t)yn0 * WIDTH + x0);
                    }
                    if (yn1 >= 0 && yn1 < HEIGHT) {
                        cp1 = *(const float2*)(P + (size_t)yn1 * WIDTH + x0);
                        ct1 = *(const float2*)(T + (size_t)yn1 * WIDTH + x0);
                    }
                }
                __syncthreads();   // row pair visible (alternating pair-buffers)

                u64 hUV[2], hQ[2];
                // ---- row A, ring slot (2p)%11 (compile-time constant) ----
                if (vA) {
                    hwin2(rA, x0, oA0, oA1, M1, hUV, hQ);
                } else {
                    hUV[0] = hUV[1] = 0; hQ[0] = hQ[1] = 0;
                }
                {
                    const int sA = (2 * p) % 11;
                    ulonglong2 q = qring[sA * NT];
                    SUV[0] = add2(SUV[0], fma2(rUV[sA][0], M1, hUV[0]));
                    SUV[1] = add2(SUV[1], fma2(rUV[sA][1], M1, hUV[1]));
                    SQ2[0] = add2(SQ2[0], fma2(q.x, M1, hQ[0]));
                    SQ2[1] = add2(SQ2[1], fma2(q.y, M1, hQ[1]));
                    rUV[sA][0] = hUV[0]; rUV[sA][1] = hUV[1];
                    qring[sA * NT] = make_ulonglong2(hQ[0], hQ[1]);
                }
                if (base >= emit0) emit2(SUV, SQ2, acc);

                // ---- row B, ring slot (2p+1)%11 ----
                if (vB) {
                    hwin2(rB, x0, oB0, oB1, M1, hUV, hQ);
                } else {
                    hUV[0] = hUV[1] = 0; hQ[0] = hQ[1] = 0;
                }
                {
                    const int sB = (2 * p + 1) % 11;
                    ulonglong2 q = qring[sB * NT];
                    SUV[0] = add2(SUV[0], fma2(rUV[sB][0], M1, hUV[0]));
                    SUV[1] = add2(SUV[1], fma2(rUV[sB][1], M1, hUV[1]));
                    SQ2[0] = add2(SQ2[0], fma2(q.x, M1, hQ[0]));
                    SQ2[1] = add2(SQ2[1], fma2(q.y, M1, hQ[1]));
                    rUV[sB][0] = hUV[0]; rUV[sB][1] = hUV[1];
                    qring[sB * NT] = make_ulonglong2(hQ[0], hQ[1]);
                }
                if (base + 1 >= emit0 && base + 1 < yend) emit2(SUV, SQ2, acc);
            }
        }
    }

    // deterministic block reduction
    red[tid] = acc;
    __syncthreads();
#pragma unroll
    for (int s = NT / 2; s > 0; s >>= 1) {
        if (tid < s) red[tid] += red[tid + s];
        __syncthreads();
    }
    if (tid == 0) {
        g_partials[bid] = red[0];
        __threadfence();
        unsigned int c = atomicAdd(&g_count, 1);
        s_last = (c == NBLOCKS - 1);
    }
    __syncthreads();
    if (s_last) {
        if (tid < 16) {
            float s = 0.f;
#pragma unroll
            for (int j = 0; j < 3 * NSTRIP; j++)
                s += __ldcg(&g_partials[tid * (3 * NSTRIP) + j]);
            out[tid] = 1.f - s * (1.f / (3.f * 512.f * 512.f));
        }
        if (tid == 0) g_count = 0;   // reset for next graph replay
    }
}

extern "C" void kernel_launch(void* const* d_in, const int* in_sizes, int n_in,
                              void* d_out, int out_size) {
    const float* pred = (const float*)d_in[0];
    const float* targ = (const float*)d_in[1];
    cudaFuncSetAttribute(ssim_main_kernel,
                         cudaFuncAttributeMaxDynamicSharedMemorySize, SMEM_SZ);
    ssim_main_kernel<<<NBLOCKS, NT, SMEM_SZ>>>(pred, targ, (float*)d_out);
}

// round 10
// speedup vs baseline: 2.3047x; 1.0007x over previous
#include <cuda_runtime.h>

// SSIM loss, fused single pass. (u,v)=(p+t,p-t) rotation, f32x2 packed.
// NT=256, 2 cols/thread, 6 strips -> grid 288 -> 2 CTAs/SM -> 4 warps/SMSP.
// 4 rows per barrier (8 row buffers), 4-row LDG prefetch (MLP=8).
// UV ring in registers (static slots); Q ring in smem. 1 rcp per 2 cols.
// Last-block finalize. pred/target: (16,3,512,512) fp32 -> out: 16 fp32.

#define WIDTH   512
#define HEIGHT  512
#define PADR    5
#define NT      256
#define NSTRIP  6
#define STRIPH  86
#define RS2     528
#define NBLOCKS (48 * NSTRIP)

// smem byte offsets (dynamic)
#define OF_Q    0              // 11*256*16 = 45056
#define OF_ROW  45056          // 8*528*8   = 33792
#define OF_RED  78848          // 256*4
#define SMEM_SZ 79872

// SSIM constants with 1/121 folded out: K1=C1*121^2, K2=C2*121^2
#define K1f 1.4641f
#define K2f 13.1769f

typedef unsigned long long u64;

__device__ float g_partials[NBLOCKS];
__device__ unsigned int g_count;

__device__ __forceinline__ u64 pk2(float a, float b) {
    u64 r; asm("mov.b64 %0,{%1,%2};" : "=l"(r) : "f"(a), "f"(b)); return r;
}
__device__ __forceinline__ float2 up2(u64 a) {
    float2 r; asm("mov.b64 {%0,%1},%2;" : "=f"(r.x), "=f"(r.y) : "l"(a)); return r;
}
__device__ __forceinline__ u64 add2(u64 a, u64 b) {
    u64 r; asm("add.rn.f32x2 %0,%1,%2;" : "=l"(r) : "l"(a), "l"(b)); return r;
}
__device__ __forceinline__ u64 mul2(u64 a, u64 b) {
    u64 r; asm("mul.rn.f32x2 %0,%1,%2;" : "=l"(r) : "l"(a), "l"(b)); return r;
}
__device__ __forceinline__ u64 fma2(u64 a, u64 b, u64 c) {
    u64 r; asm("fma.rn.f32x2 %0,%1,%2,%3;" : "=l"(r) : "l"(a), "l"(b), "l"(c)); return r;
}
__device__ __forceinline__ float rcpa(float x) {
    float r; asm("rcp.approx.f32 %0,%1;" : "=f"(r) : "f"(x)); return r;
}

// Horizontal 11-tap windows (2 chains) for 2 output columns (x0, x0+1).
// Row buffer holds packed (u,v) per col; window covers idx [x0+3, x0+14];
// own0/own1 = idx x0+8, x0+9 kept in regs.
__device__ __forceinline__ void hwin2(const float2* __restrict__ row, int x0,
                                      u64 own0, u64 own1, u64 M1,
                                      u64 hUV[2], u64 hQ[2])
{
    u64 pt[12];
    {
        ulonglong2 a = *(const ulonglong2*)(row + x0 + 2);
        ulonglong2 b = *(const ulonglong2*)(row + x0 + 4);
        ulonglong2 c = *(const ulonglong2*)(row + x0 + 6);
        pt[0] = a.y; pt[1] = b.x; pt[2] = b.y; pt[3] = c.x; pt[4] = c.y;
    }
    pt[5] = own0; pt[6] = own1;
    {
        ulonglong2 d = *(const ulonglong2*)(row + x0 + 10);
        ulonglong2 e = *(const ulonglong2*)(row + x0 + 12);
        ulonglong2 f = *(const ulonglong2*)(row + x0 + 14);
        pt[7] = d.x; pt[8] = d.y; pt[9] = e.x; pt[10] = e.y; pt[11] = f.x;
    }

    u64 s = pt[0];
    u64 q = mul2(pt[0], pt[0]);
#pragma unroll
    for (int k = 1; k < 11; k++) {
        s = add2(s, pt[k]);
        q = fma2(pt[k], pt[k], q);
    }
    hUV[0] = s; hQ[0] = q;
    // slide by one
    s = add2(s, pt[11]);
    s = fma2(pt[0], M1, s);
    q = fma2(pt[11], pt[11], q);
    q = fma2(pt[0], mul2(pt[0], M1), q);
    hUV[1] = s; hQ[1] = q;
}

// SSIM emit for 2 columns; one rcp serves both divides.
//  Su2-Sv2 = 4*Mx*My ; Su2+Sv2 = 2*(Mx^2+My^2)
//  Qu-Qv   = 4*S(pt) ; Qu+Qv   = 2*(S(p^2)+S(t^2))
__device__ __forceinline__ void emit2(const u64 SUV[2], const u64 SQ2[2], float& acc)
{
    float n[2], d[2];
#pragma unroll
    for (int c = 0; c < 2; c++) {
        float2 qf = up2(SQ2[c]);                 // (Qu, Qv)
        float2 s2 = up2(mul2(SUV[c], SUV[c]));   // (Su^2, Sv^2)
        float A = s2.x - s2.y;                   // 4*Mx*My
        float B = s2.x + s2.y;                   // 2*(Mx^2+My^2)
        float qd = qf.x - qf.y;                  // 4*S(pt)
        float qs = qf.x + qf.y;                  // 2*(Sp2+St2)
        float a  = fmaf(0.5f, A, K1f);
        float b  = fmaf(60.5f, qd, fmaf(-0.5f, A, K2f));
        n[c] = a * b;
        float d1 = fmaf(0.5f, B, K1f);
        float d2 = fmaf(60.5f, qs, fmaf(-0.5f, B, K2f));
        d[c] = d1 * d2;
    }
    float r = rcpa(d[0] * d[1]);
    acc += __saturatef(n[0] * r * d[1]) + __saturatef(n[1] * r * d[0]);
}

__global__ __launch_bounds__(NT, 2)
void ssim_main_kernel(const float* __restrict__ pred, const float* __restrict__ targ,
                      float* __restrict__ out)
{
    extern __shared__ char sm[];
    float2* rowbuf = (float2*)(sm + OF_ROW);   // 8 buffers of RS2 (u,v) packed
    float*  red    = (float*)(sm + OF_RED);
    __shared__ int s_last;

    const int tid   = threadIdx.x;
    const int bid   = blockIdx.x;
    const int img   = bid / NSTRIP;
    const int strip = bid - img * NSTRIP;
    const int r0    = strip * STRIPH;
    const int r1    = min(HEIGHT, r0 + STRIPH);
    const int yend  = r1 + PADR;
    const int emit0 = r0 + PADR;
    const int start = r0 - PADR;

    const float* __restrict__ P = pred + (size_t)img * (WIDTH * HEIGHT);
    const float* __restrict__ T = targ + (size_t)img * (WIDTH * HEIGHT);
    const int x0 = tid * 2;

    const u64 M1 = pk2(-1.f, -1.f);

    // UV ring in registers (static slots via full unroll below)
    u64 rUV[11][2];
#pragma unroll
    for (int s = 0; s < 11; s++) { rUV[s][0] = 0; rUV[s][1] = 0; }

    // Q ring in smem (per-thread slots, compile-time offsets)
    ulonglong2* qring = (ulonglong2*)(sm + OF_Q) + tid;
    {
        ulonglong2 z2 = make_ulonglong2(0ull, 0ull);
#pragma unroll
        for (int s = 0; s < 11; s++) qring[s * NT] = z2;
    }
    // zero pads of 8 row buffers: idx 3..7 (x=-5..-1) and 520..524 (x=512..516)
    if (tid < 80) {
        int r = tid / 10, k = tid % 10;
        int idx = (k < 5) ? (3 + k) : (520 + (k - 5));
        rowbuf[r * RS2 + idx] = make_float2(0.f, 0.f);
    }

    u64 SUV[2] = {0, 0}, SQ2[2] = {0, 0};
    float acc = 0.f;

    // prefetch rows start..start+3
    float2 pf_p[4] = {}, pf_t[4] = {};
#pragma unroll
    for (int r = 0; r < 4; r++) {
        int y = start + r;
        if (y >= 0 && y < HEIGHT) {
            pf_p[r] = *(const float2*)(P + (size_t)y * WIDTH + x0);
            pf_t[r] = *(const float2*)(T + (size_t)y * WIDTH + x0);
        }
    }

    __syncthreads();   // pads + zeroed ring visible

    int kpar = 0;
    for (int y0 = start; y0 < yend; y0 += 44, kpar ^= 1) {
#pragma unroll
        for (int p = 0; p < 11; p++) {
            const int base = y0 + 4 * p;
            if (base < yend) {                   // uniform across block
                const int setb = (kpar ^ (p & 1)) * 4;
                u64 own[4][2];
                bool vr[4];
                // write 4 rows into this iteration's buffer set
#pragma unroll
                for (int r = 0; r < 4; r++) {
                    const int y = base + r;
                    vr[r] = (y >= 0) && (y < HEIGHT);
                    if (vr[r]) {
                        float u0 = pf_p[r].x + pf_t[r].x, v0 = pf_p[r].x - pf_t[r].x;
                        float u1 = pf_p[r].y + pf_t[r].y, v1 = pf_p[r].y - pf_t[r].y;
                        own[r][0] = pk2(u0, v0); own[r][1] = pk2(u1, v1);
                        *(float4*)(rowbuf + (setb + r) * RS2 + x0 + 8)
                            = make_float4(u0, v0, u1, v1);
                    } else { own[r][0] = 0; own[r][1] = 0; }
                }
                __syncthreads();   // buffer set visible

                // prefetch the next 4 rows (consumed next iteration; MLP=8)
#pragma unroll
                for (int r = 0; r < 4; r++) {
                    const int y = base + 4 + r;
                    if (y >= 0 && y < HEIGHT) {
                        pf_p[r] = *(const float2*)(P + (size_t)y * WIDTH + x0);
                        pf_t[r] = *(const float2*)(T + (size_t)y * WIDTH + x0);
                    }
                }

                // process 4 rows; ring slots (4p+r)%11 are compile-time consts
#pragma unroll
                for (int r = 0; r < 4; r++) {
                    u64 hUV[2], hQ[2];
                    if (vr[r]) {
                        hwin2(rowbuf + (setb + r) * RS2, x0,
                              own[r][0], own[r][1], M1, hUV, hQ);
                    } else {
                        hUV[0] = hUV[1] = 0; hQ[0] = hQ[1] = 0;
                    }
                    const int sl = (4 * p + r) % 11;
                    ulonglong2 q = qring[sl * NT];
                    SUV[0] = add2(SUV[0], fma2(rUV[sl][0], M1, hUV[0]));
                    SUV[1] = add2(SUV[1], fma2(rUV[sl][1], M1, hUV[1]));
                    SQ2[0] = add2(SQ2[0], fma2(q.x, M1, hQ[0]));
                    SQ2[1] = add2(SQ2[1], fma2(q.y, M1, hQ[1]));
                    rUV[sl][0] = hUV[0]; rUV[sl][1] = hUV[1];
                    qring[sl * NT] = make_ulonglong2(hQ[0], hQ[1]);
                    if (base + r >= emit0 && base + r < yend)
                        emit2(SUV, SQ2, acc);
                }
            }
        }
    }

    // deterministic block reduction
    red[tid] = acc;
    __syncthreads();
#pragma unroll
    for (int s = NT / 2; s > 0; s >>= 1) {
        if (tid < s) red[tid] += red[tid + s];
        __syncthreads();
    }
    if (tid == 0) {
        g_partials[bid] = red[0];
        __threadfence();
        unsigned int c = atomicAdd(&g_count, 1);
        s_last = (c == NBLOCKS - 1);
    }
    __syncthreads();
    if (s_last) {
        if (tid < 16) {
            float s = 0.f;
#pragma unroll
            for (int j = 0; j < 3 * NSTRIP; j++)
                s += __ldcg(&g_partials[tid * (3 * NSTRIP) + j]);
            out[tid] = 1.f - s * (1.f / (3.f * 512.f * 512.f));
        }
        if (tid == 0) g_count = 0;   // reset for next graph replay
    }
}

extern "C" void kernel_launch(void* const* d_in, const int* in_sizes, int n_in,
                              void* d_out, int out_size) {
    const float* pred = (const float*)d_in[0];
    const float* targ = (const float*)d_in[1];
    cudaFuncSetAttribute(ssim_main_kernel,
                         cudaFuncAttributeMaxDynamicSharedMemorySize, SMEM_SZ);
    ssim_main_kernel<<<NBLOCKS, NT, SMEM_SZ>>>(pred, targ, (float*)d_out);
}

// round 11
// speedup vs baseline: 2.3160x; 1.0049x over previous
#include <cuda_runtime.h>

// SSIM loss, fused single pass. (u,v)=(p+t,p-t) rotation, f32x2 packed.
// Tree-structured (depth ~5) horizontal windows via shared mid-sum.
// NT=256, 2 cols/thread, 6 strips -> grid 288 -> 2 CTAs/SM -> 4 warps/SMSP.
// 4 rows per barrier (8 row buffers), 4-row LDG prefetch (MLP=8).
// UV ring in registers (static slots); Q ring in smem. 1 rcp per 2 cols.
// Last-block finalize. pred/target: (16,3,512,512) fp32 -> out: 16 fp32.

#define WIDTH   512
#define HEIGHT  512
#define PADR    5
#define NT      256
#define NSTRIP  6
#define STRIPH  86
#define RS2     528
#define NBLOCKS (48 * NSTRIP)

// smem byte offsets (dynamic)
#define OF_Q    0              // 11*256*16 = 45056
#define OF_ROW  45056          // 8*528*8   = 33792
#define OF_RED  78848          // 256*4
#define SMEM_SZ 79872

// SSIM constants with 1/121 folded out: K1=C1*121^2, K2=C2*121^2
#define K1f 1.4641f
#define K2f 13.1769f

typedef unsigned long long u64;

__device__ float g_partials[NBLOCKS];
__device__ unsigned int g_count;

__device__ __forceinline__ u64 pk2(float a, float b) {
    u64 r; asm("mov.b64 %0,{%1,%2};" : "=l"(r) : "f"(a), "f"(b)); return r;
}
__device__ __forceinline__ float2 up2(u64 a) {
    float2 r; asm("mov.b64 {%0,%1},%2;" : "=f"(r.x), "=f"(r.y) : "l"(a)); return r;
}
__device__ __forceinline__ u64 add2(u64 a, u64 b) {
    u64 r; asm("add.rn.f32x2 %0,%1,%2;" : "=l"(r) : "l"(a), "l"(b)); return r;
}
__device__ __forceinline__ u64 mul2(u64 a, u64 b) {
    u64 r; asm("mul.rn.f32x2 %0,%1,%2;" : "=l"(r) : "l"(a), "l"(b)); return r;
}
__device__ __forceinline__ u64 fma2(u64 a, u64 b, u64 c) {
    u64 r; asm("fma.rn.f32x2 %0,%1,%2,%3;" : "=l"(r) : "l"(a), "l"(b), "l"(c)); return r;
}
__device__ __forceinline__ float rcpa(float x) {
    float r; asm("rcp.approx.f32 %0,%1;" : "=f"(r) : "f"(x)); return r;
}

// Horizontal 11-tap windows for 2 output columns (x0, x0+1), tree-structured.
// Window col x0:   buffer idx [x0+3, x0+13]
// Window col x0+1: buffer idx [x0+4, x0+14]
// mid = sum over idx [x0+4, x0+13] (two independent 5-chains), shared by both.
// own0/own1 = idx x0+8, x0+9 kept in regs (not reloaded from smem).
__device__ __forceinline__ void hwin2(const float2* __restrict__ row, int x0,
                                      u64 own0, u64 own1,
                                      u64 hUV[2], u64 hQ[2])
{
    float2 eL = row[x0 + 3];
    ulonglong2 l1 = *(const ulonglong2*)(row + x0 + 4);    // idx x0+4, x0+5
    ulonglong2 l2 = *(const ulonglong2*)(row + x0 + 6);    // idx x0+6, x0+7
    ulonglong2 r1 = *(const ulonglong2*)(row + x0 + 10);   // idx x0+10, x0+11
    ulonglong2 r2 = *(const ulonglong2*)(row + x0 + 12);   // idx x0+12, x0+13
    float2 eR = row[x0 + 14];
    const u64 L0 = pk2(eL.x, eL.y);
    const u64 R5 = pk2(eR.x, eR.y);

    // sum chains (independent, depth <= 4; combine depth 6 total)
    u64 c1 = add2(add2(l1.x, l1.y), add2(l2.x, l2.y));
    c1 = add2(c1, own0);
    u64 c2 = add2(add2(own1, r1.x), add2(r1.y, r2.x));
    c2 = add2(c2, r2.y);
    u64 mid = add2(c1, c2);
    hUV[0] = add2(mid, L0);
    hUV[1] = add2(mid, R5);

    // square-sum chains (two independent fma chains, depth ~5)
    u64 q1 = fma2(l1.y, l1.y, mul2(l1.x, l1.x));
    q1 = fma2(l2.x, l2.x, q1);
    q1 = fma2(l2.y, l2.y, q1);
    q1 = fma2(own0, own0, q1);
    u64 q2 = fma2(r1.x, r1.x, mul2(own1, own1));
    q2 = fma2(r1.y, r1.y, q2);
    q2 = fma2(r2.x, r2.x, q2);
    q2 = fma2(r2.y, r2.y, q2);
    u64 midq = add2(q1, q2);
    hQ[0] = fma2(L0, L0, midq);
    hQ[1] = fma2(R5, R5, midq);
}

// SSIM emit for 2 columns; one rcp serves both divides.
//  Su2-Sv2 = 4*Mx*My ; Su2+Sv2 = 2*(Mx^2+My^2)
//  Qu-Qv   = 4*S(pt) ; Qu+Qv   = 2*(S(p^2)+S(t^2))
__device__ __forceinline__ void emit2(const u64 SUV[2], const u64 SQ2[2], float& acc)
{
    float n[2], d[2];
#pragma unroll
    for (int c = 0; c < 2; c++) {
        float2 qf = up2(SQ2[c]);                 // (Qu, Qv)
        float2 s2 = up2(mul2(SUV[c], SUV[c]));   // (Su^2, Sv^2)
        float A = s2.x - s2.y;                   // 4*Mx*My
        float B = s2.x + s2.y;                   // 2*(Mx^2+My^2)
        float qd = qf.x - qf.y;                  // 4*S(pt)
        float qs = qf.x + qf.y;                  // 2*(Sp2+St2)
        float a  = fmaf(0.5f, A, K1f);
        float b  = fmaf(60.5f, qd, fmaf(-0.5f, A, K2f));
        n[c] = a * b;
        float d1 = fmaf(0.5f, B, K1f);
        float d2 = fmaf(60.5f, qs, fmaf(-0.5f, B, K2f));
        d[c] = d1 * d2;
    }
    float r = rcpa(d[0] * d[1]);
    acc += __saturatef(n[0] * r * d[1]) + __saturatef(n[1] * r * d[0]);
}

__global__ __launch_bounds__(NT, 2)
void ssim_main_kernel(const float* __restrict__ pred, const float* __restrict__ targ,
                      float* __restrict__ out)
{
    extern __shared__ char sm[];
    float2* rowbuf = (float2*)(sm + OF_ROW);   // 8 buffers of RS2 (u,v) packed
    float*  red    = (float*)(sm + OF_RED);
    __shared__ int s_last;

    const int tid   = threadIdx.x;
    const int bid   = blockIdx.x;
    const int img   = bid / NSTRIP;
    const int strip = bid - img * NSTRIP;
    const int r0    = strip * STRIPH;
    const int r1    = min(HEIGHT, r0 + STRIPH);
    const int yend  = r1 + PADR;
    const int emit0 = r0 + PADR;
    const int start = r0 - PADR;

    const float* __restrict__ P = pred + (size_t)img * (WIDTH * HEIGHT);
    const float* __restrict__ T = targ + (size_t)img * (WIDTH * HEIGHT);
    const int x0 = tid * 2;

    const u64 M1 = pk2(-1.f, -1.f);

    // UV ring in registers (static slots via full unroll below)
    u64 rUV[11][2];
#pragma unroll
    for (int s = 0; s < 11; s++) { rUV[s][0] = 0; rUV[s][1] = 0; }

    // Q ring in smem (per-thread slots, compile-time offsets)
    ulonglong2* qring = (ulonglong2*)(sm + OF_Q) + tid;
    {
        ulonglong2 z2 = make_ulonglong2(0ull, 0ull);
#pragma unroll
        for (int s = 0; s < 11; s++) qring[s * NT] = z2;
    }
    // zero pads of 8 row buffers: idx 3..7 (x=-5..-1) and 520..524 (x=512..516)
    if (tid < 80) {
        int r = tid / 10, k = tid % 10;
        int idx = (k < 5) ? (3 + k) : (520 + (k - 5));
        rowbuf[r * RS2 + idx] = make_float2(0.f, 0.f);
    }

    u64 SUV[2] = {0, 0}, SQ2[2] = {0, 0};
    float acc = 0.f;

    // prefetch rows start..start+3
    float2 pf_p[4] = {}, pf_t[4] = {};
#pragma unroll
    for (int r = 0; r < 4; r++) {
        int y = start + r;
        if (y >= 0 && y < HEIGHT) {
            pf_p[r] = *(const float2*)(P + (size_t)y * WIDTH + x0);
            pf_t[r] = *(const float2*)(T + (size_t)y * WIDTH + x0);
        }
    }

    __syncthreads();   // pads + zeroed ring visible

    int kpar = 0;
    for (int y0 = start; y0 < yend; y0 += 44, kpar ^= 1) {
#pragma unroll
        for (int p = 0; p < 11; p++) {
            const int base = y0 + 4 * p;
            if (base < yend) {                   // uniform across block
                const int setb = (kpar ^ (p & 1)) * 4;
                u64 own[4][2];
                bool vr[4];
                // write 4 rows into this iteration's buffer set
#pragma unroll
                for (int r = 0; r < 4; r++) {
                    const int y = base + r;
                    vr[r] = (y >= 0) && (y < HEIGHT);
                    if (vr[r]) {
                        float u0 = pf_p[r].x + pf_t[r].x, v0 = pf_p[r].x - pf_t[r].x;
                        float u1 = pf_p[r].y + pf_t[r].y, v1 = pf_p[r].y - pf_t[r].y;
                        own[r][0] = pk2(u0, v0); own[r][1] = pk2(u1, v1);
                        *(float4*)(rowbuf + (setb + r) * RS2 + x0 + 8)
                            = make_float4(u0, v0, u1, v1);
                    } else { own[r][0] = 0; own[r][1] = 0; }
                }
                __syncthreads();   // buffer set visible

                // prefetch the next 4 rows (consumed next iteration; MLP=8)
#pragma unroll
                for (int r = 0; r < 4; r++) {
                    const int y = base + 4 + r;
                    if (y >= 0 && y < HEIGHT) {
                        pf_p[r] = *(const float2*)(P + (size_t)y * WIDTH + x0);
                        pf_t[r] = *(const float2*)(T + (size_t)y * WIDTH + x0);
                    }
                }

                // process 4 rows; ring slots (4p+r)%11 are compile-time consts
#pragma unroll
                for (int r = 0; r < 4; r++) {
                    u64 hUV[2], hQ[2];
                    if (vr[r]) {
                        hwin2(rowbuf + (setb + r) * RS2, x0,
                              own[r][0], own[r][1], hUV, hQ);
                    } else {
                        hUV[0] = hUV[1] = 0; hQ[0] = hQ[1] = 0;
                    }
                    const int sl = (4 * p + r) % 11;
                    ulonglong2 q = qring[sl * NT];
                    SUV[0] = add2(SUV[0], fma2(rUV[sl][0], M1, hUV[0]));
                    SUV[1] = add2(SUV[1], fma2(rUV[sl][1], M1, hUV[1]));
                    SQ2[0] = add2(SQ2[0], fma2(q.x, M1, hQ[0]));
                    SQ2[1] = add2(SQ2[1], fma2(q.y, M1, hQ[1]));
                    rUV[sl][0] = hUV[0]; rUV[sl][1] = hUV[1];
                    qring[sl * NT] = make_ulonglong2(hQ[0], hQ[1]);
                    if (base + r >= emit0 && base + r < yend)
                        emit2(SUV, SQ2, acc);
                }
            }
        }
    }

    // deterministic block reduction
    red[tid] = acc;
    __syncthreads();
#pragma unroll
    for (int s = NT / 2; s > 0; s >>= 1) {
        if (tid < s) red[tid] += red[tid + s];
        __syncthreads();
    }
    if (tid == 0) {
        g_partials[bid] = red[0];
        __threadfence();
        unsigned int c = atomicAdd(&g_count, 1);
        s_last = (c == NBLOCKS - 1);
    }
    __syncthreads();
    if (s_last) {
        if (tid < 16) {
            float s = 0.f;
#pragma unroll
            for (int j = 0; j < 3 * NSTRIP; j++)
                s += __ldcg(&g_partials[tid * (3 * NSTRIP) + j]);
            out[tid] = 1.f - s * (1.f / (3.f * 512.f * 512.f));
        }
        if (tid == 0) g_count = 0;   // reset for next graph replay
    }
}

extern "C" void kernel_launch(void* const* d_in, const int* in_sizes, int n_in,
                              void* d_out, int out_size) {
    const float* pred = (const float*)d_in[0];
    const float* targ = (const float*)d_in[1];
    cudaFuncSetAttribute(ssim_main_kernel,
                         cudaFuncAttributeMaxDynamicSharedMemorySize, SMEM_SZ);
    ssim_main_kernel<<<NBLOCKS, NT, SMEM_SZ>>>(pred, targ, (float*)d_out);
}